// round 8
// baseline (speedup 1.0000x reference)
#include <cuda_runtime.h>

// Problem constants (from reference)
#define BATCH   1024
#define NK      33          // ykinput rows = 33; nonzero support width (2*16+1)
#define COLBASE 4080        // VECCNTR - 1 - 15
#define VEC     8192
#define EPSF    0.01f

#define NBLOCKS 128         // one wave; best measured config
#define NTHREADS 256        // 8 warps per block, one warp per batch row
#define WPB     8

__device__ float        g_total = 0.0f;
__device__ unsigned int g_count = 0;

__global__ void __launch_bounds__(NTHREADS)
ngl_kernel(const float* __restrict__ input,
           const float* __restrict__ output,
           const float* __restrict__ ykinput,
           float* __restrict__ out)
{
    __shared__ float wsum_s[WPB];

    const int tid  = threadIdx.x;
    const int warp = tid >> 5;
    const int lane = tid & 31;
    const int row  = blockIdx.x * WPB + warp;   // one warp per batch row

    // ---- Issue ALL global loads up front (hidden under the conv chain) ----
    // Lane l owns yk row k=l in registers (rows 0..31).
    const float* ybase = ykinput + lane * VEC + COLBASE;   // 16B-aligned
    float y[NK];
    #pragma unroll
    for (int q = 0; q < 8; ++q) {
        const float4 v = *reinterpret_cast<const float4*>(ybase + 4 * q);
        y[4 * q + 0] = v.x; y[4 * q + 1] = v.y;
        y[4 * q + 2] = v.z; y[4 * q + 3] = v.w;
    }
    y[32] = ybase[32];

    // Row k=32 is handled distributed: lane l gets y32[2l-2], y32[2l-1]
    // (its own coefficient slots). Lanes whose slots fall outside [0,32]
    // have e=o=0 forever, so any in-bounds value is harmless.
    const float* y32b = ykinput + 32 * VEC + COLBASE;      // 8B-aligned steps
    const int l1 = (lane == 0) ? 0 : (lane - 1);
    const float2 y32p = *reinterpret_cast<const float2*>(y32b + 2 * l1);
    // psi for row 32 needs y32[15..17]; uniform-address loads (warp broadcast).
    const float y32a = y32b[15], y32bv = y32b[16], y32c = y32b[17];

    // Per-row parameters (uniform across the warp)
    const float4 in4 = *reinterpret_cast<const float4*>(input + row * 4);
    const float p0 = in4.x, p1 = in4.y, p2 = in4.z;
    const int   m  = (int)in4.w;                // 1..16, exact in fp32
    const float o0 = output[row * 3 + 0];
    const float o1 = output[row * 3 + 1];
    const float o2 = output[row * 3 + 2];

    // ---- Lane-distributed (m-1)-fold 3-tap convolution ---------------------
    // Shifted mapping: lane l owns e = c[2l-2], o = c[2l-1].
    // Support stays in c[0..32] (lanes 1..17); boundary lanes hold structural
    // zeros forever -> no predicates on the dependency chain.
    float e = 0.0f, o = 0.0f;
    if (lane == 8) { o = p0; }               // c[15]
    if (lane == 9) { e = p1; o = p2; }       // c[16], c[17]

    for (int t = 0; t < m - 1; ++t) {
        const float se = fmaf(p1, e, p2 * o);     // off-chain partial of e_new
        const float so = fmaf(p0, e, p1 * o);     // off-chain partial of o_new
        const float o_up = __shfl_up_sync(0xffffffffu, o, 1);   // c[2l-3]
        const float e_dn = __shfl_down_sync(0xffffffffu, e, 1); // c[2l]
        e = fmaf(p0, o_up, se);              // chain: shfl + 1 FMA
        o = fmaf(p2, e_dn, so);
    }

    // ---- Dot for k = lane: coefficients via warp broadcast (no smem) -------
    // c[j] lives in lane (j+2)>>1: even j -> e, odd j -> o. Compile-time
    // selection after full unroll; 33 pipelined shfl broadcasts.
    float pa = 0.0f, pb = 0.0f;
    #pragma unroll
    for (int j = 0; j < NK; ++j) {
        const int src = (j + 2) >> 1;
        const float c = __shfl_sync(0xffffffffu, (j & 1) ? o : e, src);
        if (j & 1) pb = fmaf(c, y[j], pb);
        else       pa = fmaf(c, y[j], pa);
    }
    const float p = pa + pb;
    const float psi = fmaf(o0, y[15], fmaf(o1, y[16], o2 * y[17]));
    const float d = p - psi;
    const float q = 1.0f - p;
    float lsum = __fdividef(d * d, fmaf(q, q, EPSF));

    // ---- Row k=32: distributed partial products, butterfly to everyone -----
    float part32 = fmaf(e, y32p.x, o * y32p.y);
    #pragma unroll
    for (int off = 16; off; off >>= 1)
        part32 += __shfl_xor_sync(0xffffffffu, part32, off);
    {
        const float psi32 = fmaf(o0, y32a, fmaf(o1, y32bv, o2 * y32c));
        const float d32 = part32 - psi32;
        const float q32 = 1.0f - part32;
        const float t32 = __fdividef(d32 * d32, fmaf(q32, q32, EPSF));
        if (lane == 0) lsum += t32;
    }

    // ---- Warp reduction -----------------------------------------------------
    #pragma unroll
    for (int off = 16; off; off >>= 1)
        lsum += __shfl_down_sync(0xffffffffu, lsum, off);
    if (lane == 0)
        wsum_s[warp] = lsum;
    __syncthreads();                         // the ONLY block barrier

    // ---- One global atomic per block (measured-best tail) ------------------
    if (tid == 0) {
        float bs = 0.0f;
        #pragma unroll
        for (int w = 0; w < WPB; ++w) bs += wsum_s[w];
        atomicAdd(&g_total, bs);
        __threadfence();                      // release: my add before my count
        unsigned int old = atomicAdd(&g_count, 1u);
        if (old == (unsigned int)(NBLOCKS - 1)) {
            __threadfence();                  // acquire: all adds visible
            *out = *((volatile float*)&g_total);
            g_total = 0.0f;                   // re-arm for next graph replay
            g_count = 0u;
        }
    }
}

extern "C" void kernel_launch(void* const* d_in, const int* in_sizes, int n_in,
                              void* d_out, int out_size)
{
    const float* input   = (const float*)d_in[0];   // (1024, 4)
    const float* output  = (const float*)d_in[1];   // (1024, 3)
    const float* ykinput = (const float*)d_in[2];   // (33, 8192)
    float* out = (float*)d_out;                     // scalar loss
    (void)in_sizes; (void)n_in; (void)out_size;

    ngl_kernel<<<NBLOCKS, NTHREADS>>>(input, output, ykinput, out);
}